// round 3
// baseline (speedup 1.0000x reference)
#include <cuda_runtime.h>
#include <cstdint>

// FANSNeuralOutputUpdate on GB300 (sm_103a), round 2.
// y[b,g] = tanh(z @ W1[g] + b1[g]) @ W2[g] + b2[g]
// f32x2 packing over BATCH pairs {b, b+1}: weights shared across the packed
// dim (duplicated in smem once), z loaded as one LDS.64 from a transposed
// x tile. tanh via single MUFU.TANH (tanh.approx.f32).

#define B_TILE   128    // batches per block
#define NG       8      // groups per block (one per warp)
#define NJ       2      // batch-pairs per lane (covers 4 batches/lane)
#define THREADS  256
#define XSTRIDE  130    // transposed x tile row stride (even -> 8B-aligned pairs)

typedef unsigned long long ull;

__device__ __forceinline__ ull pack2(float lo, float hi) {
    ull r; asm("mov.b64 %0, {%1, %2};" : "=l"(r) : "f"(lo), "f"(hi)); return r;
}
__device__ __forceinline__ void unpack2(ull v, float& lo, float& hi) {
    asm("mov.b64 {%0, %1}, %2;" : "=f"(lo), "=f"(hi) : "l"(v));
}
__device__ __forceinline__ ull ffma2(ull a, ull b, ull c) {
    ull d; asm("fma.rn.f32x2 %0, %1, %2, %3;" : "=l"(d) : "l"(a), "l"(b), "l"(c)); return d;
}
__device__ __forceinline__ float tanh_hw(float x) {
    float r; asm("tanh.approx.f32 %0, %1;" : "=f"(r) : "f"(x)); return r;
}

__global__ __launch_bounds__(THREADS, 3)
void fans_kernel(const float* __restrict__ x_f,     // (B,16)
                 const float* __restrict__ x_b,     // (B,16)
                 const int*   __restrict__ sel_idx, // (64,8)
                 const float* __restrict__ W1,      // (64,8,32)
                 const float* __restrict__ b1,      // (64,32)
                 const float* __restrict__ W2,      // (64,32,1)
                 const float* __restrict__ b2,      // (64,1)
                 float*       __restrict__ out,     // (B,64)
                 int Btot)
{
    __shared__ float xs[32 * XSTRIDE];      // transposed: xs[col][batch]
    __shared__ ull   wp [NG][8][32];        // {w,w} duplicated
    __shared__ ull   b1p[NG][32];           // {b1,b1}
    __shared__ ull   w2p[NG][32];           // {w2,w2}
    __shared__ int   sels[NG][8];
    __shared__ float b2s[NG];
    __shared__ float ys[B_TILE * 9];        // [batch][group], pad 9

    const int tid    = threadIdx.x;
    const int batch0 = blockIdx.x * B_TILE;
    const int g0     = blockIdx.y * NG;

    // ---- stage x tile TRANSPOSED: xs[j][bl] = x[batch0+bl][j] ----
    for (int i = tid; i < B_TILE * 32; i += THREADS) {
        int bl = i >> 5, j = i & 31;            // global read coalesced over j
        int bg = batch0 + bl;
        float v = 0.0f;
        if (bg < Btot)
            v = (j < 16) ? x_f[bg * 16 + j] : x_b[bg * 16 + (j - 16)];
        xs[j * XSTRIDE + bl] = v;
    }
    // ---- stage duplicated weights for this block's 8 groups ----
    for (int i = tid; i < NG * 8 * 32; i += THREADS) {
        int gl = i >> 8, r = i & 255;
        int k = r >> 5, h = r & 31;
        float w = W1[((g0 + gl) * 8 + k) * 32 + h];
        wp[gl][k][h] = pack2(w, w);
    }
    for (int i = tid; i < NG * 32; i += THREADS) {
        int gl = i >> 5, h = i & 31;
        float bb = b1[(g0 + gl) * 32 + h];
        float ww = W2[(g0 + gl) * 32 + h];
        b1p[gl][h] = pack2(bb, bb);
        w2p[gl][h] = pack2(ww, ww);
    }
    if (tid < NG * 8) {
        int gl = tid >> 3, k = tid & 7;
        sels[gl][k] = sel_idx[(g0 + gl) * 8 + k];
    }
    if (tid < NG) b2s[tid] = b2[g0 + tid];
    __syncthreads();

    const int wid = tid >> 5, lane = tid & 31;

    // ---- z: one LDS.64 per (j,k): {x[2p][col], x[2p+1][col]} ----
    ull z2[NJ][8];
#pragma unroll
    for (int k = 0; k < 8; k++) {
        const float* colp = &xs[sels[wid][k] * XSTRIDE];
#pragma unroll
        for (int j = 0; j < NJ; j++) {
            int p = lane + 32 * j;              // pair index: batches (2p, 2p+1)
            z2[j][k] = *(const ull*)&colp[2 * p];
        }
    }

    ull y2[NJ];
    {
        float bv = b2s[wid];
        ull b2v = pack2(bv, bv);
#pragma unroll
        for (int j = 0; j < NJ; j++) y2[j] = b2v;
    }

    // ---- main loop over hidden units ----
#pragma unroll 4
    for (int h = 0; h < 32; h++) {
        ull wk[8];
#pragma unroll
        for (int k = 0; k < 8; k++) wk[k] = wp[wid][k][h];   // broadcast LDS.64
        ull accinit = b1p[wid][h];
        ull w2k     = w2p[wid][h];
#pragma unroll
        for (int j = 0; j < NJ; j++) {
            ull acc = accinit;
#pragma unroll
            for (int k = 0; k < 8; k++)
                acc = ffma2(z2[j][k], wk[k], acc);           // 2 batches/instr
            float a, b;
            unpack2(acc, a, b);
            y2[j] = ffma2(pack2(tanh_hw(a), tanh_hw(b)), w2k, y2[j]);
        }
    }

    // ---- stage results, then coalesced full-sector writes ----
#pragma unroll
    for (int j = 0; j < NJ; j++) {
        int p = lane + 32 * j;
        float a, b;
        unpack2(y2[j], a, b);
        ys[(2 * p)     * 9 + wid] = a;
        ys[(2 * p + 1) * 9 + wid] = b;
    }
    __syncthreads();

    for (int e = tid; e < B_TILE * NG; e += THREADS) {
        int bl = e >> 3, c = e & 7;             // 8 consecutive cols = 32B sector
        int bg = batch0 + bl;
        if (bg < Btot)
            out[bg * 64 + g0 + c] = ys[bl * 9 + c];
    }
}

extern "C" void kernel_launch(void* const* d_in, const int* in_sizes, int n_in,
                              void* d_out, int out_size)
{
    const float* x_f = (const float*)d_in[0];
    const float* x_b = (const float*)d_in[1];
    const int*   sel = (const int*)  d_in[2];
    const float* W1  = (const float*)d_in[3];
    const float* b1  = (const float*)d_in[4];
    const float* W2  = (const float*)d_in[5];
    const float* b2  = (const float*)d_in[6];
    float*       out = (float*)d_out;

    int Btot = in_sizes[0] / 16;                         // 65536
    dim3 grid((Btot + B_TILE - 1) / B_TILE, 64 / NG);    // (512, 8)
    fans_kernel<<<grid, THREADS>>>(x_f, x_b, sel, W1, b1, W2, b2, out, Btot);
}

// round 4
// speedup vs baseline: 1.7531x; 1.7531x over previous
#include <cuda_runtime.h>
#include <cstdint>

// FANSNeuralOutputUpdate on GB300 (sm_103a), round 3.
// Round-1 skeleton (group-pair f32x2 FFMA2, NB=4 independent batch chains)
// + tanh.approx.f32 (validated rel_err ~3e-6)
// + weight layout [g][h][k] -> 5 LDS per h (4x LDS.128 wk + 1x LDS.128 {b1,w2})
// + k-chain split in two halves (dep depth 32 -> 21 cyc).

#define B_TILE     128   // batches per block
#define GP_BLOCK   8     // group-pairs per block (warp w handles (gp0+w, gp0+w+32))
#define NB         4     // batches per thread (lane + 32*j)
#define THREADS    256

typedef unsigned long long ull;

__device__ __forceinline__ ull pack2(float lo, float hi) {
    ull r; asm("mov.b64 %0, {%1, %2};" : "=l"(r) : "f"(lo), "f"(hi)); return r;
}
__device__ __forceinline__ void unpack2(ull v, float& lo, float& hi) {
    asm("mov.b64 {%0, %1}, %2;" : "=f"(lo), "=f"(hi) : "l"(v));
}
__device__ __forceinline__ ull ffma2(ull a, ull b, ull c) {
    ull d; asm("fma.rn.f32x2 %0, %1, %2, %3;" : "=l"(d) : "l"(a), "l"(b), "l"(c)); return d;
}
__device__ __forceinline__ ull fadd2(ull a, ull b) {
    ull d; asm("add.rn.f32x2 %0, %1, %2;" : "=l"(d) : "l"(a), "l"(b)); return d;
}
__device__ __forceinline__ float tanh_hw(float x) {
    float r; asm("tanh.approx.f32 %0, %1;" : "=f"(r) : "f"(x)); return r;
}

__global__ __launch_bounds__(THREADS, 2)
void fans_kernel(const float* __restrict__ x_f,     // (B,16)
                 const float* __restrict__ x_b,     // (B,16)
                 const int*   __restrict__ sel_idx, // (64,8)
                 const float* __restrict__ W1,      // (64,8,32)
                 const float* __restrict__ b1,      // (64,32)
                 const float* __restrict__ W2,      // (64,32,1)
                 const float* __restrict__ b2,      // (64,1)
                 float*       __restrict__ out,     // (B,64)
                 int Btot)
{
    __shared__ float xs[B_TILE * 33];                 // row-major, stride 33
    __shared__ __align__(16) ull  wp[GP_BLOCK][32][8];   // [g][h][k], {W1[g],W1[g+32]}
    __shared__ __align__(16) ull  bw[GP_BLOCK][32][2];   // [g][h] -> {b1 pair, w2 pair}
    __shared__ int   sels[GP_BLOCK][8];
    __shared__ ull   b2p[GP_BLOCK];
    __shared__ float ys[B_TILE * 17];

    const int tid    = threadIdx.x;
    const int batch0 = blockIdx.x * B_TILE;
    const int gp0    = blockIdx.y * GP_BLOCK;

    // ---- stage x tile (coalesced over j) ----
    for (int i = tid; i < B_TILE * 32; i += THREADS) {
        int bl = i >> 5, j = i & 31;
        int bg = batch0 + bl;
        float v = 0.0f;
        if (bg < Btot)
            v = (j < 16) ? x_f[bg * 16 + j] : x_b[bg * 16 + (j - 16)];
        xs[bl * 33 + j] = v;
    }
    // ---- stage packed W1, layout [g][h][k] ----
    for (int i = tid; i < GP_BLOCK * 32 * 8; i += THREADS) {
        int gpl = i >> 8, r = i & 255;
        int h = r >> 3, k = r & 7;
        int gA = gp0 + gpl, gB = gA + 32;
        wp[gpl][h][k] = pack2(W1[(gA * 8 + k) * 32 + h], W1[(gB * 8 + k) * 32 + h]);
    }
    // ---- stage fused {b1 pair, w2 pair} ----
    for (int i = tid; i < GP_BLOCK * 32; i += THREADS) {
        int gpl = i >> 5, h = i & 31;
        int gA = gp0 + gpl, gB = gA + 32;
        bw[gpl][h][0] = pack2(b1[gA * 32 + h], b1[gB * 32 + h]);
        bw[gpl][h][1] = pack2(W2[gA * 32 + h], W2[gB * 32 + h]);
    }
    if (tid < GP_BLOCK * 8) {
        int gpl = tid >> 3, k = tid & 7;
        sels[gpl][k] = sel_idx[(gp0 + gpl) * 8 + k];   // sel[g] == sel[g+32]
    }
    if (tid < GP_BLOCK)
        b2p[tid] = pack2(b2[gp0 + tid], b2[gp0 + tid + 32]);
    __syncthreads();

    const int wid = tid >> 5, lane = tid & 31;

    // ---- z duplicated into both f32x2 halves (needed for group-pair FFMA2) ----
    int col[8];
#pragma unroll
    for (int k = 0; k < 8; k++) col[k] = sels[wid][k];

    ull z2[NB][8];
#pragma unroll
    for (int j = 0; j < NB; j++) {
        const float* row = &xs[(lane + 32 * j) * 33];
#pragma unroll
        for (int k = 0; k < 8; k++) {
            float v = row[col[k]];
            z2[j][k] = pack2(v, v);
        }
    }

    ull y2[NB];
    {
        ull b2v = b2p[wid];
#pragma unroll
        for (int j = 0; j < NB; j++) y2[j] = b2v;
    }

    // ---- main loop over hidden units ----
#pragma unroll 2
    for (int h = 0; h < 32; h++) {
        // 4x LDS.128: 8 packed weights for this h (warp-uniform -> broadcast)
        ulonglong2 w01 = *(const ulonglong2*)&wp[wid][h][0];
        ulonglong2 w23 = *(const ulonglong2*)&wp[wid][h][2];
        ulonglong2 w45 = *(const ulonglong2*)&wp[wid][h][4];
        ulonglong2 w67 = *(const ulonglong2*)&wp[wid][h][6];
        ulonglong2 bwv = *(const ulonglong2*)&bw[wid][h][0];  // {b1p, w2p}
#pragma unroll
        for (int j = 0; j < NB; j++) {
            // two independent 4-deep chains, then one add
            ull a0 = ffma2(z2[j][0], w01.x, bwv.x);
            ull a1 = ffma2(z2[j][4], w45.x, ffma2(z2[j][5], w45.y,
                      ffma2(z2[j][6], w67.x, ffma2(z2[j][7], w67.y,
                      pack2(0.0f, 0.0f)))));
            a0 = ffma2(z2[j][1], w01.y, a0);
            a0 = ffma2(z2[j][2], w23.x, a0);
            a0 = ffma2(z2[j][3], w23.y, a0);
            ull acc = fadd2(a0, a1);
            float a, b;
            unpack2(acc, a, b);
            y2[j] = ffma2(pack2(tanh_hw(a), tanh_hw(b)), bwv.y, y2[j]);
        }
    }

    // ---- stage results, then full-sector coalesced writes ----
#pragma unroll
    for (int j = 0; j < NB; j++) {
        int bl = lane + 32 * j;
        float a, b;
        unpack2(y2[j], a, b);
        ys[bl * 17 + wid]     = a;   // column gp0+wid
        ys[bl * 17 + 8 + wid] = b;   // column gp0+wid+32
    }
    __syncthreads();

    for (int e = tid; e < B_TILE * 16; e += THREADS) {
        int bl = e >> 4, c = e & 15;
        int bg = batch0 + bl;
        if (bg < Btot) {
            int colg = gp0 + ((c < 8) ? c : (c + 24));
            out[bg * 64 + colg] = ys[bl * 17 + c];
        }
    }
}

extern "C" void kernel_launch(void* const* d_in, const int* in_sizes, int n_in,
                              void* d_out, int out_size)
{
    const float* x_f = (const float*)d_in[0];
    const float* x_b = (const float*)d_in[1];
    const int*   sel = (const int*)  d_in[2];
    const float* W1  = (const float*)d_in[3];
    const float* b1  = (const float*)d_in[4];
    const float* W2  = (const float*)d_in[5];
    const float* b2  = (const float*)d_in[6];
    float*       out = (float*)d_out;

    int Btot = in_sizes[0] / 16;                                   // 65536
    dim3 grid((Btot + B_TILE - 1) / B_TILE, 64 / (2 * GP_BLOCK));  // (512, 4)
    fans_kernel<<<grid, THREADS>>>(x_f, x_b, sel, W1, b1, W2, b2, out, Btot);
}

// round 5
// speedup vs baseline: 1.9194x; 1.0949x over previous
#include <cuda_runtime.h>
#include <cstdint>

// FANSNeuralOutputUpdate on GB300 (sm_103a), round 4.
// k-packed f32x2 (no z duplication): z2k[j][kk] = {z[2kk], z[2kk+1]}.
// Warp owns group pair (g, g+32) (shared sel => shared z regs), two
// independent 4-deep FFMA2 chains per j seeded with {b1/2, b1/2} so the
// horizontal sum is one scalar FADD. NB=2, B_TILE=64, 3 CTAs/SM target.

#define B_TILE     64    // batches per block
#define GP_BLOCK   8     // group-pairs per block (warp w -> (gp0+w, gp0+w+32))
#define NB         2     // batch rows per lane
#define THREADS    256
#define WH_STRIDE  12    // ull per (g,h) record: wA[4], wB[4], b1h[2], w2p, pad

typedef unsigned long long ull;

__device__ __forceinline__ ull pack2(float lo, float hi) {
    ull r; asm("mov.b64 %0, {%1, %2};" : "=l"(r) : "f"(lo), "f"(hi)); return r;
}
__device__ __forceinline__ void unpack2(ull v, float& lo, float& hi) {
    asm("mov.b64 {%0, %1}, %2;" : "=f"(lo), "=f"(hi) : "l"(v));
}
__device__ __forceinline__ ull ffma2(ull a, ull b, ull c) {
    ull d; asm("fma.rn.f32x2 %0, %1, %2, %3;" : "=l"(d) : "l"(a), "l"(b), "l"(c)); return d;
}
__device__ __forceinline__ float tanh_hw(float x) {
    float r; asm("tanh.approx.f32 %0, %1;" : "=f"(r) : "f"(x)); return r;
}

__global__ __launch_bounds__(THREADS, 3)
void fans_kernel(const float* __restrict__ x_f,     // (B,16)
                 const float* __restrict__ x_b,     // (B,16)
                 const int*   __restrict__ sel_idx, // (64,8)
                 const float* __restrict__ W1,      // (64,8,32)
                 const float* __restrict__ b1,      // (64,32)
                 const float* __restrict__ W2,      // (64,32,1)
                 const float* __restrict__ b2,      // (64,1)
                 float*       __restrict__ out,     // (B,64)
                 int Btot)
{
    __shared__ float xs[B_TILE * 33];                     // row-major, stride 33
    __shared__ __align__(16) ull wh[GP_BLOCK][32][WH_STRIDE];
    __shared__ int   sels[GP_BLOCK][8];
    __shared__ ull   b2p[GP_BLOCK];
    __shared__ float ys[B_TILE * 17];

    const int tid    = threadIdx.x;
    const int batch0 = blockIdx.x * B_TILE;
    const int gp0    = blockIdx.y * GP_BLOCK;

    // ---- stage x tile (coalesced over j) ----
    for (int i = tid; i < B_TILE * 32; i += THREADS) {
        int bl = i >> 5, j = i & 31;
        int bg = batch0 + bl;
        float v = 0.0f;
        if (bg < Btot)
            v = (j < 16) ? x_f[bg * 16 + j] : x_b[bg * 16 + (j - 16)];
        xs[bl * 33 + j] = v;
    }

    // ---- stage weight records: one thread per (gpl, h) ----
    {
        int gpl = tid >> 5, h = tid & 31;      // 256 threads == 8*32 records
        int gA = gp0 + gpl, gB = gA + 32;
        ull* rec = wh[gpl][h];
#pragma unroll
        for (int kk = 0; kk < 4; kk++) {
            rec[kk]     = pack2(W1[(gA * 8 + 2 * kk) * 32 + h],
                                W1[(gA * 8 + 2 * kk + 1) * 32 + h]);
            rec[4 + kk] = pack2(W1[(gB * 8 + 2 * kk) * 32 + h],
                                W1[(gB * 8 + 2 * kk + 1) * 32 + h]);
        }
        float bA = 0.5f * b1[gA * 32 + h];
        float bB = 0.5f * b1[gB * 32 + h];
        rec[8] = pack2(bA, bA);                // seed chain A: {b1A/2, b1A/2}
        rec[9] = pack2(bB, bB);                // seed chain B
        rec[10] = pack2(W2[gA * 32 + h], W2[gB * 32 + h]);
    }
    if (tid < GP_BLOCK * 8) {
        int gpl = tid >> 3, k = tid & 7;
        sels[gpl][k] = sel_idx[(gp0 + gpl) * 8 + k];   // sel[g] == sel[g+32]
    }
    if (tid < GP_BLOCK)
        b2p[tid] = pack2(b2[gp0 + tid], b2[gp0 + tid + 32]);
    __syncthreads();

    const int wid = tid >> 5, lane = tid & 31;

    int col[8];
#pragma unroll
    for (int k = 0; k < 8; k++) col[k] = sels[wid][k];

    // ---- z, k-packed: {z[2kk], z[2kk+1]} ----
    ull z2[NB][4];
#pragma unroll
    for (int j = 0; j < NB; j++) {
        const float* row = &xs[(lane + 32 * j) * 33];
#pragma unroll
        for (int kk = 0; kk < 4; kk++)
            z2[j][kk] = pack2(row[col[2 * kk]], row[col[2 * kk + 1]]);
    }

    ull y2[NB];
    {
        ull b2v = b2p[wid];
#pragma unroll
        for (int j = 0; j < NB; j++) y2[j] = b2v;
    }

    // ---- main loop over hidden units ----
#pragma unroll 2
    for (int h = 0; h < 32; h++) {
        const ull* rec = wh[wid][h];
        ulonglong2 wa01 = *(const ulonglong2*)&rec[0];
        ulonglong2 wa23 = *(const ulonglong2*)&rec[2];
        ulonglong2 wb01 = *(const ulonglong2*)&rec[4];
        ulonglong2 wb23 = *(const ulonglong2*)&rec[6];
        ulonglong2 bb   = *(const ulonglong2*)&rec[8];   // {b1hA, b1hB}
        ull        w2p  = rec[10];
#pragma unroll
        for (int j = 0; j < NB; j++) {
            ull accA = ffma2(z2[j][0], wa01.x, bb.x);
            accA = ffma2(z2[j][1], wa01.y, accA);
            accA = ffma2(z2[j][2], wa23.x, accA);
            accA = ffma2(z2[j][3], wa23.y, accA);
            ull accB = ffma2(z2[j][0], wb01.x, bb.y);
            accB = ffma2(z2[j][1], wb01.y, accB);
            accB = ffma2(z2[j][2], wb23.x, accB);
            accB = ffma2(z2[j][3], wb23.y, accB);
            float aLo, aHi, bLo, bHi;
            unpack2(accA, aLo, aHi);
            unpack2(accB, bLo, bHi);
            float tA = tanh_hw(aLo + aHi);     // seeds were b1/2 each half
            float tB = tanh_hw(bLo + bHi);
            y2[j] = ffma2(pack2(tA, tB), w2p, y2[j]);
        }
    }

    // ---- stage results, then full-sector coalesced writes ----
#pragma unroll
    for (int j = 0; j < NB; j++) {
        int bl = lane + 32 * j;
        float a, b;
        unpack2(y2[j], a, b);
        ys[bl * 17 + wid]     = a;   // column gp0+wid
        ys[bl * 17 + 8 + wid] = b;   // column gp0+wid+32
    }
    __syncthreads();

    for (int e = tid; e < B_TILE * 16; e += THREADS) {
        int bl = e >> 4, c = e & 15;
        int bg = batch0 + bl;
        if (bg < Btot) {
            int colg = gp0 + ((c < 8) ? c : (c + 24));
            out[bg * 64 + colg] = ys[bl * 17 + c];
        }
    }
}

extern "C" void kernel_launch(void* const* d_in, const int* in_sizes, int n_in,
                              void* d_out, int out_size)
{
    const float* x_f = (const float*)d_in[0];
    const float* x_b = (const float*)d_in[1];
    const int*   sel = (const int*)  d_in[2];
    const float* W1  = (const float*)d_in[3];
    const float* b1  = (const float*)d_in[4];
    const float* W2  = (const float*)d_in[5];
    const float* b2  = (const float*)d_in[6];
    float*       out = (float*)d_out;

    int Btot = in_sizes[0] / 16;                                   // 65536
    dim3 grid((Btot + B_TILE - 1) / B_TILE, 64 / (2 * GP_BLOCK));  // (1024, 4)
    fans_kernel<<<grid, THREADS>>>(x_f, x_b, sel, W1, b1, W2, b2, out, Btot);
}

// round 6
// speedup vs baseline: 2.0778x; 1.0825x over previous
#include <cuda_runtime.h>
#include <cstdint>

// FANSNeuralOutputUpdate on GB300 (sm_103a), round 5.
// R4 structure (k-packed f32x2, group-pair per warp, b1/2 seed trick)
// + register diet: h-loop unroll 1 + __launch_bounds__(256,4)
//   -> <=64 regs -> 4 CTAs/SM (32 warps) vs 3 (24 warps).

#define B_TILE     64    // batches per block
#define GP_BLOCK   8     // group-pairs per block (warp w -> (gp0+w, gp0+w+32))
#define NB         2     // batch rows per lane
#define THREADS    256
#define WH_STRIDE  12    // ull per (g,h) record: wA[4], wB[4], b1h[2], w2p, pad

typedef unsigned long long ull;

__device__ __forceinline__ ull pack2(float lo, float hi) {
    ull r; asm("mov.b64 %0, {%1, %2};" : "=l"(r) : "f"(lo), "f"(hi)); return r;
}
__device__ __forceinline__ void unpack2(ull v, float& lo, float& hi) {
    asm("mov.b64 {%0, %1}, %2;" : "=f"(lo), "=f"(hi) : "l"(v));
}
__device__ __forceinline__ ull ffma2(ull a, ull b, ull c) {
    ull d; asm("fma.rn.f32x2 %0, %1, %2, %3;" : "=l"(d) : "l"(a), "l"(b), "l"(c)); return d;
}
__device__ __forceinline__ float tanh_hw(float x) {
    float r; asm("tanh.approx.f32 %0, %1;" : "=f"(r) : "f"(x)); return r;
}

__global__ __launch_bounds__(THREADS, 4)
void fans_kernel(const float* __restrict__ x_f,     // (B,16)
                 const float* __restrict__ x_b,     // (B,16)
                 const int*   __restrict__ sel_idx, // (64,8)
                 const float* __restrict__ W1,      // (64,8,32)
                 const float* __restrict__ b1,      // (64,32)
                 const float* __restrict__ W2,      // (64,32,1)
                 const float* __restrict__ b2,      // (64,1)
                 float*       __restrict__ out,     // (B,64)
                 int Btot)
{
    __shared__ float xs[B_TILE * 33];                     // row-major, stride 33
    __shared__ __align__(16) ull wh[GP_BLOCK][32][WH_STRIDE];
    __shared__ int   sels[GP_BLOCK][8];
    __shared__ ull   b2p[GP_BLOCK];
    __shared__ float ys[B_TILE * 17];

    const int tid    = threadIdx.x;
    const int batch0 = blockIdx.x * B_TILE;
    const int gp0    = blockIdx.y * GP_BLOCK;

    // ---- stage x tile (coalesced over j) ----
    for (int i = tid; i < B_TILE * 32; i += THREADS) {
        int bl = i >> 5, j = i & 31;
        int bg = batch0 + bl;
        float v = 0.0f;
        if (bg < Btot)
            v = (j < 16) ? x_f[bg * 16 + j] : x_b[bg * 16 + (j - 16)];
        xs[bl * 33 + j] = v;
    }

    // ---- stage weight records: one thread per (gpl, h) ----
    {
        int gpl = tid >> 5, h = tid & 31;      // 256 threads == 8*32 records
        int gA = gp0 + gpl, gB = gA + 32;
        ull* rec = wh[gpl][h];
#pragma unroll
        for (int kk = 0; kk < 4; kk++) {
            rec[kk]     = pack2(W1[(gA * 8 + 2 * kk) * 32 + h],
                                W1[(gA * 8 + 2 * kk + 1) * 32 + h]);
            rec[4 + kk] = pack2(W1[(gB * 8 + 2 * kk) * 32 + h],
                                W1[(gB * 8 + 2 * kk + 1) * 32 + h]);
        }
        float bA = 0.5f * b1[gA * 32 + h];
        float bB = 0.5f * b1[gB * 32 + h];
        rec[8] = pack2(bA, bA);                // seed chain A: {b1A/2, b1A/2}
        rec[9] = pack2(bB, bB);                // seed chain B
        rec[10] = pack2(W2[gA * 32 + h], W2[gB * 32 + h]);
    }
    if (tid < GP_BLOCK * 8) {
        int gpl = tid >> 3, k = tid & 7;
        sels[gpl][k] = sel_idx[(gp0 + gpl) * 8 + k];   // sel[g] == sel[g+32]
    }
    if (tid < GP_BLOCK)
        b2p[tid] = pack2(b2[gp0 + tid], b2[gp0 + tid + 32]);
    __syncthreads();

    const int wid = tid >> 5, lane = tid & 31;

    int col[8];
#pragma unroll
    for (int k = 0; k < 8; k++) col[k] = sels[wid][k];

    // ---- z, k-packed: {z[2kk], z[2kk+1]} ----
    ull z2[NB][4];
#pragma unroll
    for (int j = 0; j < NB; j++) {
        const float* row = &xs[(lane + 32 * j) * 33];
#pragma unroll
        for (int kk = 0; kk < 4; kk++)
            z2[j][kk] = pack2(row[col[2 * kk]], row[col[2 * kk + 1]]);
    }

    ull y2[NB];
    {
        ull b2v = b2p[wid];
#pragma unroll
        for (int j = 0; j < NB; j++) y2[j] = b2v;
    }

    // ---- main loop over hidden units (unroll 1: keep live regs small) ----
#pragma unroll 1
    for (int h = 0; h < 32; h++) {
        const ull* rec = wh[wid][h];
        ulonglong2 wa01 = *(const ulonglong2*)&rec[0];
        ulonglong2 wa23 = *(const ulonglong2*)&rec[2];
        ulonglong2 wb01 = *(const ulonglong2*)&rec[4];
        ulonglong2 wb23 = *(const ulonglong2*)&rec[6];
        ulonglong2 bb   = *(const ulonglong2*)&rec[8];   // {b1hA, b1hB}
        ull        w2p  = rec[10];
#pragma unroll
        for (int j = 0; j < NB; j++) {
            ull accA = ffma2(z2[j][0], wa01.x, bb.x);
            accA = ffma2(z2[j][1], wa01.y, accA);
            accA = ffma2(z2[j][2], wa23.x, accA);
            accA = ffma2(z2[j][3], wa23.y, accA);
            ull accB = ffma2(z2[j][0], wb01.x, bb.y);
            accB = ffma2(z2[j][1], wb01.y, accB);
            accB = ffma2(z2[j][2], wb23.x, accB);
            accB = ffma2(z2[j][3], wb23.y, accB);
            float aLo, aHi, bLo, bHi;
            unpack2(accA, aLo, aHi);
            unpack2(accB, bLo, bHi);
            float tA = tanh_hw(aLo + aHi);     // seeds were b1/2 each half
            float tB = tanh_hw(bLo + bHi);
            y2[j] = ffma2(pack2(tA, tB), w2p, y2[j]);
        }
    }

    // ---- stage results, then full-sector coalesced writes ----
#pragma unroll
    for (int j = 0; j < NB; j++) {
        int bl = lane + 32 * j;
        float a, b;
        unpack2(y2[j], a, b);
        ys[bl * 17 + wid]     = a;   // column gp0+wid
        ys[bl * 17 + 8 + wid] = b;   // column gp0+wid+32
    }
    __syncthreads();

    for (int e = tid; e < B_TILE * 16; e += THREADS) {
        int bl = e >> 4, c = e & 15;
        int bg = batch0 + bl;
        if (bg < Btot) {
            int colg = gp0 + ((c < 8) ? c : (c + 24));
            out[bg * 64 + colg] = ys[bl * 17 + c];
        }
    }
}

extern "C" void kernel_launch(void* const* d_in, const int* in_sizes, int n_in,
                              void* d_out, int out_size)
{
    const float* x_f = (const float*)d_in[0];
    const float* x_b = (const float*)d_in[1];
    const int*   sel = (const int*)  d_in[2];
    const float* W1  = (const float*)d_in[3];
    const float* b1  = (const float*)d_in[4];
    const float* W2  = (const float*)d_in[5];
    const float* b2  = (const float*)d_in[6];
    float*       out = (float*)d_out;

    int Btot = in_sizes[0] / 16;                                   // 65536
    dim3 grid((Btot + B_TILE - 1) / B_TILE, 64 / (2 * GP_BLOCK));  // (1024, 4)
    fans_kernel<<<grid, THREADS>>>(x_f, x_b, sel, W1, b1, W2, b2, out, Btot);
}

// round 9
// speedup vs baseline: 2.1441x; 1.0319x over previous
#include <cuda_runtime.h>
#include <cstdint>

// FANSNeuralOutputUpdate on GB300 (sm_103a), round 6.
// R5 structure (k-packed f32x2, group-pair per warp, b1/2 seed, unroll 1,
// 4 CTAs/SM) + NB=3 (B_TILE=96): amortize per-h fixed cost (6 LDS + loop
// ALU) over 3 batches instead of 2, and 6 independent FFMA2 chains per h.

#define B_TILE     96    // batches per block (= 32 lanes * NB)
#define GP_BLOCK   8     // group-pairs per block (warp w -> (gp0+w, gp0+w+32))
#define NB         3     // batch rows per lane
#define THREADS    256
#define WH_STRIDE  12    // ull per (g,h) record: wA[4], wB[4], b1h[2], w2p, pad

typedef unsigned long long ull;

__device__ __forceinline__ ull pack2(float lo, float hi) {
    ull r; asm("mov.b64 %0, {%1, %2};" : "=l"(r) : "f"(lo), "f"(hi)); return r;
}
__device__ __forceinline__ void unpack2(ull v, float& lo, float& hi) {
    asm("mov.b64 {%0, %1}, %2;" : "=f"(lo), "=f"(hi) : "l"(v));
}
__device__ __forceinline__ ull ffma2(ull a, ull b, ull c) {
    ull d; asm("fma.rn.f32x2 %0, %1, %2, %3;" : "=l"(d) : "l"(a), "l"(b), "l"(c)); return d;
}
__device__ __forceinline__ float tanh_hw(float x) {
    float r; asm("tanh.approx.f32 %0, %1;" : "=f"(r) : "f"(x)); return r;
}

__global__ __launch_bounds__(THREADS, 4)
void fans_kernel(const float* __restrict__ x_f,     // (B,16)
                 const float* __restrict__ x_b,     // (B,16)
                 const int*   __restrict__ sel_idx, // (64,8)
                 const float* __restrict__ W1,      // (64,8,32)
                 const float* __restrict__ b1,      // (64,32)
                 const float* __restrict__ W2,      // (64,32,1)
                 const float* __restrict__ b2,      // (64,1)
                 float*       __restrict__ out,     // (B,64)
                 int Btot)
{
    __shared__ float xs[B_TILE * 33];                     // row-major, stride 33
    __shared__ __align__(16) ull wh[GP_BLOCK][32][WH_STRIDE];
    __shared__ int   sels[GP_BLOCK][8];
    __shared__ ull   b2p[GP_BLOCK];
    __shared__ float ys[B_TILE * 17];

    const int tid    = threadIdx.x;
    const int batch0 = blockIdx.x * B_TILE;
    const int gp0    = blockIdx.y * GP_BLOCK;

    // ---- stage x tile (coalesced over j) ----
    for (int i = tid; i < B_TILE * 32; i += THREADS) {
        int bl = i >> 5, j = i & 31;
        int bg = batch0 + bl;
        float v = 0.0f;
        if (bg < Btot)
            v = (j < 16) ? x_f[bg * 16 + j] : x_b[bg * 16 + (j - 16)];
        xs[bl * 33 + j] = v;
    }

    // ---- stage weight records: one thread per (gpl, h) ----
    {
        int gpl = tid >> 5, h = tid & 31;      // 256 threads == 8*32 records
        int gA = gp0 + gpl, gB = gA + 32;
        ull* rec = wh[gpl][h];
#pragma unroll
        for (int kk = 0; kk < 4; kk++) {
            rec[kk]     = pack2(W1[(gA * 8 + 2 * kk) * 32 + h],
                                W1[(gA * 8 + 2 * kk + 1) * 32 + h]);
            rec[4 + kk] = pack2(W1[(gB * 8 + 2 * kk) * 32 + h],
                                W1[(gB * 8 + 2 * kk + 1) * 32 + h]);
        }
        float bA = 0.5f * b1[gA * 32 + h];
        float bB = 0.5f * b1[gB * 32 + h];
        rec[8] = pack2(bA, bA);                // seed chain A: {b1A/2, b1A/2}
        rec[9] = pack2(bB, bB);                // seed chain B
        rec[10] = pack2(W2[gA * 32 + h], W2[gB * 32 + h]);
    }
    if (tid < GP_BLOCK * 8) {
        int gpl = tid >> 3, k = tid & 7;
        sels[gpl][k] = sel_idx[(gp0 + gpl) * 8 + k];   // sel[g] == sel[g+32]
    }
    if (tid < GP_BLOCK)
        b2p[tid] = pack2(b2[gp0 + tid], b2[gp0 + tid + 32]);
    __syncthreads();

    const int wid = tid >> 5, lane = tid & 31;

    int col[8];
#pragma unroll
    for (int k = 0; k < 8; k++) col[k] = sels[wid][k];

    // ---- z, k-packed: {z[2kk], z[2kk+1]} (prologue; col regs die here) ----
    ull z2[NB][4];
#pragma unroll
    for (int j = 0; j < NB; j++) {
        const float* row = &xs[(lane + 32 * j) * 33];
#pragma unroll
        for (int kk = 0; kk < 4; kk++)
            z2[j][kk] = pack2(row[col[2 * kk]], row[col[2 * kk + 1]]);
    }

    ull y2[NB];
    {
        ull b2v = b2p[wid];
#pragma unroll
        for (int j = 0; j < NB; j++) y2[j] = b2v;
    }

    // ---- main loop over hidden units (unroll 1: keep live regs small) ----
#pragma unroll 1
    for (int h = 0; h < 32; h++) {
        const ull* rec = wh[wid][h];
        ulonglong2 wa01 = *(const ulonglong2*)&rec[0];
        ulonglong2 wa23 = *(const ulonglong2*)&rec[2];
        ulonglong2 wb01 = *(const ulonglong2*)&rec[4];
        ulonglong2 wb23 = *(const ulonglong2*)&rec[6];
        ulonglong2 bb   = *(const ulonglong2*)&rec[8];   // {b1hA, b1hB}
        ull        w2p  = rec[10];
#pragma unroll
        for (int j = 0; j < NB; j++) {
            ull accA = ffma2(z2[j][0], wa01.x, bb.x);
            accA = ffma2(z2[j][1], wa01.y, accA);
            accA = ffma2(z2[j][2], wa23.x, accA);
            accA = ffma2(z2[j][3], wa23.y, accA);
            ull accB = ffma2(z2[j][0], wb01.x, bb.y);
            accB = ffma2(z2[j][1], wb01.y, accB);
            accB = ffma2(z2[j][2], wb23.x, accB);
            accB = ffma2(z2[j][3], wb23.y, accB);
            float aLo, aHi, bLo, bHi;
            unpack2(accA, aLo, aHi);
            unpack2(accB, bLo, bHi);
            float tA = tanh_hw(aLo + aHi);     // seeds were b1/2 each half
            float tB = tanh_hw(bLo + bHi);
            y2[j] = ffma2(pack2(tA, tB), w2p, y2[j]);
        }
    }

    // ---- stage results, then full-sector coalesced writes ----
#pragma unroll
    for (int j = 0; j < NB; j++) {
        int bl = lane + 32 * j;
        float a, b;
        unpack2(y2[j], a, b);
        ys[bl * 17 + wid]     = a;   // column gp0+wid
        ys[bl * 17 + 8 + wid] = b;   // column gp0+wid+32
    }
    __syncthreads();

    for (int e = tid; e < B_TILE * 16; e += THREADS) {
        int bl = e >> 4, c = e & 15;
        int bg = batch0 + bl;
        if (bg < Btot) {
            int colg = gp0 + ((c < 8) ? c : (c + 24));
            out[bg * 64 + colg] = ys[bl * 17 + c];
        }
    }
}

extern "C" void kernel_launch(void* const* d_in, const int* in_sizes, int n_in,
                              void* d_out, int out_size)
{
    const float* x_f = (const float*)d_in[0];
    const float* x_b = (const float*)d_in[1];
    const int*   sel = (const int*)  d_in[2];
    const float* W1  = (const float*)d_in[3];
    const float* b1  = (const float*)d_in[4];
    const float* W2  = (const float*)d_in[5];
    const float* b2  = (const float*)d_in[6];
    float*       out = (float*)d_out;

    int Btot = in_sizes[0] / 16;                                   // 65536
    dim3 grid((Btot + B_TILE - 1) / B_TILE, 64 / (2 * GP_BLOCK));  // (683, 4)
    fans_kernel<<<grid, THREADS>>>(x_f, x_b, sel, W1, b1, W2, b2, out, Btot);
}